// round 5
// baseline (speedup 1.0000x reference)
#include <cuda_runtime.h>

#define NS 200000
#define NA 400000
#define NU 200000
#define HH 64
#define ESS 2000000
#define EAS 4000000
#define EUS 2000000
#define NB 196                 // ceil(NS/1024) scan blocks
#define GEMM_TILES 3125        // NS/64
#define GEMM_SMEM ((4*64*64 + 64*65 + 64)*4)

typedef unsigned long long ull;

// ---------------- static device scratch (no allocations allowed) ----------------
__device__ __align__(256) float g_agg_ss[NS*HH];
__device__ __align__(256) float g_agg_as[NS*HH];
__device__ __align__(256) float g_agg_us[NS*HH];
__device__ __align__(256) float g_sub0[NS*HH];
__device__ __align__(256) float g_sub1[NS*HH];
__device__ int g_csr_ss[ESS];
__device__ int g_csr_as[EAS];
__device__ int g_csr_us[EUS];
__device__ int g_off_ss[NS+1];
__device__ int g_off_as[NS+1];
__device__ int g_off_us[NS+1];
__device__ int g_cur_ss[NS];
__device__ int g_cur_as[NS];
__device__ int g_cur_us[NS];
__device__ int g_part[3*256];
__device__ __align__(16) float g_W[3*4*HH*HH];   // [layer][r][k][o], r: 0=Wl_ss 1=Wl_as 2=Wl_us 3=Wr_sum
__device__ float g_bias[3*HH];

// ---------------- helpers ----------------
__device__ __forceinline__ int* rel_cur(int rel){ return rel==0? g_cur_ss : rel==1? g_cur_as : g_cur_us; }
__device__ __forceinline__ int* rel_off(int rel){ return rel==0? g_off_ss : rel==1? g_off_as : g_off_us; }
__device__ __forceinline__ int* rel_csr(int rel){ return rel==0? g_csr_ss : rel==1? g_csr_as : g_csr_us; }

// ---------------- weight prep: transpose + fold Wr/bias sums ----------------
__global__ void k_prep(const float* __restrict__ Wl, const float* __restrict__ bl,
                       const float* __restrict__ Wr)
{
    int idx = blockIdx.x*blockDim.x + threadIdx.x;
    if (idx < 3*4*64*64){
        int o = idx & 63;
        int k = (idx>>6) & 63;
        int r = (idx>>12) & 3;
        int l = idx>>14;
        float w;
        if (r < 3) w = Wl[(((size_t)l*3 + r)*64 + o)*64 + k];
        else       w = Wr[(((size_t)l*3 + 0)*64 + o)*64 + k]
                     + Wr[(((size_t)l*3 + 1)*64 + o)*64 + k]
                     + Wr[(((size_t)l*3 + 2)*64 + o)*64 + k];
        g_W[idx] = w;
    }
    if (idx < 3*64){
        int l = idx>>6, o = idx&63;
        g_bias[idx] = bl[(l*3+0)*64+o] + bl[(l*3+1)*64+o] + bl[(l*3+2)*64+o];
    }
}

__global__ void k_zero()
{
    for (int i = blockIdx.x*blockDim.x + threadIdx.x; i < NS; i += gridDim.x*blockDim.x){
        g_cur_ss[i]=0; g_cur_as[i]=0; g_cur_us[i]=0;
    }
}

// ---------------- CSR build ----------------
__global__ void k_count(const int* __restrict__ dst, int E, int rel)
{
    int* cur = rel_cur(rel);
    for (int e = blockIdx.x*blockDim.x + threadIdx.x; e < E; e += gridDim.x*blockDim.x)
        atomicAdd(&cur[__ldg(&dst[e])], 1);
}

__global__ void k_scan_local(int rel)
{
    const int* deg = rel_cur(rel);
    int* off = rel_off(rel);
    int* part = g_part + rel*256;
    __shared__ int s[2][1024];
    int t = threadIdx.x;
    int i = blockIdx.x*1024 + t;
    int v = (i < NS) ? deg[i] : 0;
    int pa = 0;
    s[0][t] = v;
    __syncthreads();
    #pragma unroll
    for (int d = 1; d < 1024; d <<= 1){
        int val = s[pa][t];
        if (t >= d) val += s[pa][t-d];
        s[pa^1][t] = val;
        pa ^= 1;
        __syncthreads();
    }
    int inc = s[pa][t];
    if (i < NS) off[i] = inc - v;        // block-local exclusive
    if (t == 1023) part[blockIdx.x] = inc;
}

__global__ void k_scan_part(int rel)
{
    if (threadIdx.x == 0 && blockIdx.x == 0){
        int* part = g_part + rel*256;
        int* off = rel_off(rel);
        int run = 0;
        for (int b = 0; b < NB; b++){ int t = part[b]; part[b] = run; run += t; }
        off[NS] = run;
    }
}

__global__ void k_scan_add(int rel)
{
    int* off = rel_off(rel);
    int* cur = rel_cur(rel);
    const int* part = g_part + rel*256;
    int i = blockIdx.x*1024 + threadIdx.x;
    if (i < NS){
        int v = off[i] + part[blockIdx.x];
        off[i] = v;
        cur[i] = v;       // cursor for fill
    }
}

__global__ void k_fill(const int* __restrict__ src, const int* __restrict__ dst, int E, int rel)
{
    int* cur = rel_cur(rel);
    int* csr = rel_csr(rel);
    for (int e = blockIdx.x*blockDim.x + threadIdx.x; e < E; e += gridDim.x*blockDim.x){
        int d = __ldg(&dst[e]);
        int p = atomicAdd(&cur[d], 1);
        csr[p] = __ldg(&src[e]);
    }
}

// ---------------- segment gather (one warp per destination node) ----------------
__global__ void k_gather(const float* __restrict__ xext, int xsel, int rel, int meanflag, int outsel)
{
    const float* x = xsel==0 ? xext : (xsel==1 ? g_sub0 : g_sub1);
    float* op = outsel==0 ? g_agg_ss : (outsel==1 ? g_agg_as : g_agg_us);
    const int* csr = rel_csr(rel);
    const int* off = rel_off(rel);

    int warp = (blockIdx.x*blockDim.x + threadIdx.x) >> 5;
    int lane = threadIdx.x & 31;
    if (warp >= NS) return;
    int b = __ldg(&off[warp]);
    int e = __ldg(&off[warp+1]);
    const float2* x2 = (const float2*)x;
    float ax = 0.f, ay = 0.f;
    int i = b;
    // 2-way unrolled for MLP
    for (; i + 2 <= e; i += 2){
        int s0 = __ldg(&csr[i]);
        int s1 = __ldg(&csr[i+1]);
        float2 v0 = __ldg(&x2[(size_t)s0*32 + lane]);
        float2 v1 = __ldg(&x2[(size_t)s1*32 + lane]);
        ax += v0.x + v1.x; ay += v0.y + v1.y;
    }
    if (i < e){
        int s0 = __ldg(&csr[i]);
        float2 v0 = __ldg(&x2[(size_t)s0*32 + lane]);
        ax += v0.x; ay += v0.y;
    }
    if (meanflag && e > b){ float sc = 1.f/(float)(e-b); ax *= sc; ay *= sc; }
    ((float2*)op)[(size_t)warp*32 + lane] = make_float2(ax, ay);
}

// ---------------- fused layer GEMM: out = relu([agg_ss|agg_as|agg_us|sub] @ Wcat + b) ----------------
__global__ void __launch_bounds__(256,2)
k_gemm(const float* __restrict__ sub_ext, int sub_sel, int out_sel, int layer)
{
    extern __shared__ float sm[];
    float* Ws = sm;                    // 4*64*64
    float* Xs = sm + 16384;            // 64*65
    float* Bs = sm + 16384 + 64*65;    // 64

    const int tid = threadIdx.x;
    const int tx = tid & 15;           // output group: outs tx*4..tx*4+3
    const int ty = tid >> 4;           // node group:  nodes ty + 16*mi

    for (int j = tid; j < 16384; j += 256) Ws[j] = g_W[layer*16384 + j];
    if (tid < 64) Bs[tid] = g_bias[layer*64 + tid];

    const float* Asub = sub_sel==0 ? sub_ext : (sub_sel==1 ? g_sub0 : g_sub1);
    float* outp = out_sel==0 ? g_sub0 : g_sub1;

    for (int tile = blockIdx.x; tile < GEMM_TILES; tile += gridDim.x){
        const int base = tile*64;
        ull acc[4][2];
        #pragma unroll
        for (int mi = 0; mi < 4; mi++){ acc[mi][0] = 0ull; acc[mi][1] = 0ull; }

        #pragma unroll
        for (int r = 0; r < 4; r++){
            const float* A = (r==0) ? g_agg_ss : (r==1) ? g_agg_as : (r==2) ? g_agg_us : Asub;
            __syncthreads();   // protect Xs from previous k-loop readers
            #pragma unroll
            for (int j = tid; j < 1024; j += 256){
                int node = j >> 4, c = j & 15;
                float4 v = *(const float4*)(A + ((size_t)(base+node))*64 + c*4);
                float* d = &Xs[node*65 + c*4];
                d[0]=v.x; d[1]=v.y; d[2]=v.z; d[3]=v.w;
            }
            __syncthreads();
            const float* wr = Ws + r*4096 + tx*4;
            const float* xr = Xs + ty*65;
            #pragma unroll 16
            for (int k = 0; k < 64; k++){
                const ull* wp = (const ull*)(wr + k*64);
                ull wa = wp[0], wb = wp[1];
                #pragma unroll
                for (int mi = 0; mi < 4; mi++){
                    float xv = xr[mi*16*65 + k];
                    ull xp;
                    asm("mov.b64 %0, {%1, %1};" : "=l"(xp) : "f"(xv));
                    asm("fma.rn.f32x2 %0, %1, %2, %0;" : "+l"(acc[mi][0]) : "l"(xp), "l"(wa));
                    asm("fma.rn.f32x2 %0, %1, %2, %0;" : "+l"(acc[mi][1]) : "l"(xp), "l"(wb));
                }
            }
        }
        float b0 = Bs[tx*4+0], b1 = Bs[tx*4+1], b2 = Bs[tx*4+2], b3 = Bs[tx*4+3];
        #pragma unroll
        for (int mi = 0; mi < 4; mi++){
            float x0,x1,x2,x3;
            asm("mov.b64 {%0, %1}, %2;" : "=f"(x0), "=f"(x1) : "l"(acc[mi][0]));
            asm("mov.b64 {%0, %1}, %2;" : "=f"(x2), "=f"(x3) : "l"(acc[mi][1]));
            float4 o;
            o.x = fmaxf(x0 + b0, 0.f);
            o.y = fmaxf(x1 + b1, 0.f);
            o.z = fmaxf(x2 + b2, 0.f);
            o.w = fmaxf(x3 + b3, 0.f);
            *(float4*)(outp + ((size_t)(base + ty + 16*mi))*64 + tx*4) = o;
        }
    }
}

// ---------------- head: softmax(sub @ Wf.T + bf) ----------------
__global__ void k_head(const float* __restrict__ Wf, const float* __restrict__ bf,
                       float* __restrict__ out, int sub_sel)
{
    const float* sub = sub_sel==1 ? g_sub0 : g_sub1;
    int warp = (blockIdx.x*blockDim.x + threadIdx.x) >> 5;
    int lane = threadIdx.x & 31;
    if (warp >= NS) return;
    float2 xv = *(const float2*)(sub + (size_t)warp*64 + lane*2);
    float p[6];
    #pragma unroll
    for (int o = 0; o < 6; o++){
        float w0 = __ldg(&Wf[o*64 + lane*2]);
        float w1 = __ldg(&Wf[o*64 + lane*2 + 1]);
        p[o] = xv.x*w0 + xv.y*w1;
    }
    #pragma unroll
    for (int s = 16; s; s >>= 1){
        #pragma unroll
        for (int o = 0; o < 6; o++) p[o] += __shfl_xor_sync(0xffffffffu, p[o], s);
    }
    float m = -1e30f;
    #pragma unroll
    for (int o = 0; o < 6; o++){ p[o] += __ldg(&bf[o]); m = fmaxf(m, p[o]); }
    float s = 0.f;
    #pragma unroll
    for (int o = 0; o < 6; o++){ p[o] = expf(p[o] - m); s += p[o]; }
    float inv = 1.f/s;
    if (lane == 0){
        #pragma unroll
        for (int o = 0; o < 6; o++) out[(size_t)warp*6 + o] = p[o]*inv;
    }
}

// ---------------- launch ----------------
extern "C" void kernel_launch(void* const* d_in, const int* in_sizes, int n_in,
                              void* d_out, int out_size)
{
    const float* x_sub   = (const float*)d_in[0];
    const float* x_agr   = (const float*)d_in[1];
    const float* x_urb   = (const float*)d_in[2];
    const float* Wl      = (const float*)d_in[3];
    const float* bl      = (const float*)d_in[4];
    const float* Wr      = (const float*)d_in[5];
    const float* Wf      = (const float*)d_in[6];
    const float* bf      = (const float*)d_in[7];
    const int*   e_ss    = (const int*)d_in[8];
    const int*   e_as_s  = (const int*)d_in[9];
    const int*   e_as_d  = (const int*)d_in[10];
    const int*   e_us    = (const int*)d_in[11];
    float* out = (float*)d_out;

    cudaFuncSetAttribute(k_gemm, cudaFuncAttributeMaxDynamicSharedMemorySize, GEMM_SMEM);

    k_prep<<<192,256>>>(Wl, bl, Wr);
    k_zero<<<196,1024>>>();

    k_count<<<2048,256>>>(e_ss + ESS, ESS, 0);
    k_count<<<2048,256>>>(e_as_d,     EAS, 1);
    k_count<<<2048,256>>>(e_us + EUS, EUS, 2);

    for (int r = 0; r < 3; r++){
        k_scan_local<<<NB,1024>>>(r);
        k_scan_part<<<1,32>>>(r);
        k_scan_add<<<NB,1024>>>(r);
    }

    k_fill<<<2048,256>>>(e_ss,   e_ss + ESS, ESS, 0);
    k_fill<<<2048,256>>>(e_as_s, e_as_d,     EAS, 1);
    k_fill<<<2048,256>>>(e_us,   e_us + EUS, EUS, 2);

    // layer-invariant aggregations (agr->sub, urb->sub), computed once
    k_gather<<<25000,256>>>(x_agr, 0, 1, 0, 1);
    k_gather<<<25000,256>>>(x_urb, 0, 2, 0, 2);

    // layer 0: sum aggregation, sub input = x_sub, out -> g_sub0
    k_gather<<<25000,256>>>(x_sub, 0, 0, 0, 0);
    k_gemm<<<296,256,GEMM_SMEM>>>(x_sub, 0, 0, 0);
    // layer 1: mean aggregation, sub input = g_sub0, out -> g_sub1
    k_gather<<<25000,256>>>(nullptr, 1, 0, 1, 0);
    k_gemm<<<296,256,GEMM_SMEM>>>(nullptr, 1, 1, 1);
    // layer 2: mean aggregation, sub input = g_sub1, out -> g_sub0
    k_gather<<<25000,256>>>(nullptr, 2, 0, 1, 0);
    k_gemm<<<296,256,GEMM_SMEM>>>(nullptr, 2, 0, 2);

    k_head<<<25000,256>>>(Wf, bf, out, 1);
}